// round 1
// baseline (speedup 1.0000x reference)
#include <cuda_runtime.h>

// GlobalFilter: out = irfft2( rfft2(x, ortho) * w, ortho ) per (b, c) on 14x14 grid.
// Collapses to: unnormalized DFT -> *w -> unnormalized inverse DFT * (1/196).
//
// One CTA handles (batch b, 64-channel block). 128 threads: thread = (c in 0..63, h in {0,1}).
// Shared tile S[a1][slot(16)][c]: slots 0..13 hold spatial row, then 0..7 = Re(k2), 8..15 = Im(k2).
// All DFT loops fully unrolled; coefficients are compile-time literals -> FFMA immediates.

#define CB 64
#define THREADS 128
#define SMEM_BYTES (14 * 16 * CB * 4)

// cos/sin(2*pi*t/14), t = 0..13
__device__ constexpr float C14[14] = {
     1.0f,
     0.9009688679024191f,  0.6234898018587336f,  0.22252093395631445f,
    -0.22252093395631434f, -0.6234898018587335f, -0.9009688679024190f,
    -1.0f,
    -0.9009688679024191f, -0.6234898018587336f, -0.22252093395631445f,
     0.22252093395631434f,  0.6234898018587335f,  0.9009688679024190f
};
__device__ constexpr float S14[14] = {
     0.0f,
     0.4338837391175581f,  0.7818314824680298f,  0.9749279121818236f,
     0.9749279121818236f,  0.7818314824680299f,  0.4338837391175582f,
     0.0f,
    -0.4338837391175581f, -0.7818314824680298f, -0.9749279121818236f,
    -0.9749279121818236f, -0.7818314824680299f, -0.4338837391175582f
};

extern "C" __global__ void __launch_bounds__(THREADS)
gf_kernel(const float* __restrict__ x,
          const float* __restrict__ w,
          float* __restrict__ out)
{
    extern __shared__ float S[];   // [14][16][CB]

    const int b    = blockIdx.x;        // 0..511
    const int c0   = blockIdx.y * CB;   // channel block base
    const int tid  = threadIdx.x;
    const int c    = tid & (CB - 1);    // 0..63
    const int h    = tid >> 6;          // 0/1 (row/col half split)

    // ---------------- load x[b, :, c0+c] into smem grid ----------------
    const float* xb = x + (size_t)b * 196 * 384 + (c0 + c);
    #pragma unroll 2
    for (int n = h * 98; n < h * 98 + 98; ++n) {
        S[((n / 14) * 16 + (n % 14)) * CB + c] = xb[(size_t)n * 384];
    }
    __syncthreads();

    // ---------------- stage 1: rfft along rows (a2 -> k2) ----------------
    for (int a1 = h * 7; a1 < h * 7 + 7; ++a1) {
        float r[14];
        #pragma unroll
        for (int j = 0; j < 14; ++j) r[j] = S[(a1 * 16 + j) * CB + c];

        float re[8], im[8];
        #pragma unroll
        for (int k = 0; k < 8; ++k) {
            float sr = 0.f, si = 0.f;
            #pragma unroll
            for (int j = 0; j < 14; ++j) {
                const int t = (j * k) % 14;
                sr += r[j] * C14[t];
                si -= r[j] * S14[t];
            }
            re[k] = sr; im[k] = si;
        }
        #pragma unroll
        for (int k = 0; k < 8; ++k) {
            S[(a1 * 16 + k)     * CB + c] = re[k];
            S[(a1 * 16 + 8 + k) * CB + c] = im[k];
        }
    }
    __syncthreads();

    // ------- stages 2+3+4: per-column complex fft -> *w -> complex ifft (in registers) -------
    for (int k2 = h * 4; k2 < h * 4 + 4; ++k2) {
        float yr[14], yi[14];
        #pragma unroll
        for (int j = 0; j < 14; ++j) {
            yr[j] = S[(j * 16 + k2)     * CB + c];
            yi[j] = S[(j * 16 + 8 + k2) * CB + c];
        }

        float orr[14], oii[14];
        #pragma unroll
        for (int a1 = 0; a1 < 14; ++a1) { orr[a1] = 0.f; oii[a1] = 0.f; }

        #pragma unroll
        for (int k1 = 0; k1 < 14; ++k1) {
            // forward DFT along a1 (e^{-i theta}): X = sum y * (c - i s)
            float Xr = 0.f, Xi = 0.f;
            #pragma unroll
            for (int j = 0; j < 14; ++j) {
                const int t = (j * k1) % 14;
                Xr += yr[j] * C14[t] + yi[j] * S14[t];
                Xi += yi[j] * C14[t] - yr[j] * S14[t];
            }
            // multiply by complex weight  w[k1][k2][c0+c]
            const float2 wv = *(const float2*)(w + ((size_t)(k1 * 8 + k2) * 384 + (c0 + c)) * 2);
            const float Zr = Xr * wv.x - Xi * wv.y;
            const float Zi = Xr * wv.y + Xi * wv.x;
            // inverse DFT along a1 (e^{+i theta}), accumulated as outer product
            #pragma unroll
            for (int a1 = 0; a1 < 14; ++a1) {
                const int t = (k1 * a1) % 14;
                orr[a1] += Zr * C14[t] - Zi * S14[t];
                oii[a1] += Zi * C14[t] + Zr * S14[t];
            }
        }

        #pragma unroll
        for (int a1 = 0; a1 < 14; ++a1) {
            S[(a1 * 16 + k2)     * CB + c] = orr[a1];
            S[(a1 * 16 + 8 + k2) * CB + c] = oii[a1];
        }
    }
    __syncthreads();

    // ---------------- stage 5: irfft along rows (k2 -> a2), scale 1/196, store ----------------
    float* ob = out + (size_t)b * 196 * 384 + (c0 + c);
    for (int a1 = h * 7; a1 < h * 7 + 7; ++a1) {
        float zr[8], zi[8];
        #pragma unroll
        for (int k = 0; k < 8; ++k) {
            zr[k] = S[(a1 * 16 + k)     * CB + c];
            zi[k] = S[(a1 * 16 + 8 + k) * CB + c];
        }
        #pragma unroll
        for (int a2 = 0; a2 < 14; ++a2) {
            float v = zr[0] + ((a2 & 1) ? -zr[7] : zr[7]);
            #pragma unroll
            for (int k = 1; k < 7; ++k) {
                const int t = (k * a2) % 14;
                v += 2.0f * (zr[k] * C14[t] - zi[k] * S14[t]);
            }
            ob[(size_t)(a1 * 14 + a2) * 384] = v * (1.0f / 196.0f);
        }
    }
}

extern "C" void kernel_launch(void* const* d_in, const int* in_sizes, int n_in,
                              void* d_out, int out_size)
{
    const float* x = (const float*)d_in[0];   // [512,196,384] f32
    const float* w = (const float*)d_in[1];   // [14,8,384,2]  f32
    float* out = (float*)d_out;               // [512,196,384] f32

    cudaFuncSetAttribute(gf_kernel, cudaFuncAttributeMaxDynamicSharedMemorySize, SMEM_BYTES);

    dim3 grid(512, 384 / CB);   // (batch, channel block)
    gf_kernel<<<grid, THREADS, SMEM_BYTES>>>(x, w, out);
}

// round 3
// speedup vs baseline: 2.5207x; 2.5207x over previous
#include <cuda_runtime.h>

// GlobalFilter via packed f32x2 arithmetic: each thread handles TWO adjacent
// channels in one 64-bit register lane-pair. out = IDFT2( DFT2(x) * w ) / 196.
//
// CTA = (batch, 64-channel block). 128 threads = 32 lane-pairs x 4 work groups (h).
// smem tile S[a1(14)][slot(16)][lane(32)] of ull (packed 2xf32): 57344 B.
//   slots 0..13: spatial row  /  after stage1: 0..7 Re(k2), 8..15 Im(k2).
// Middle stage: phase A (fwd DFT + weight -> Z back into same slots, rows=k1),
//               phase B (inverse DFT accumulate <- Z). No sync needed between
//               A and B (slot ownership is per-thread).

typedef unsigned long long ull;

// cos/sin(2*pi*t/14) as constexpr functions -> always compile-time literals.
__host__ __device__ constexpr float C14f(int t) {
    constexpr float v[14] = {
         1.0f,
         0.9009688679024191f,  0.6234898018587336f,  0.22252093395631445f,
        -0.22252093395631434f, -0.6234898018587335f, -0.9009688679024190f,
        -1.0f,
        -0.9009688679024191f, -0.6234898018587336f, -0.22252093395631445f,
         0.22252093395631434f,  0.6234898018587335f,  0.9009688679024190f
    };
    return v[t];
}
__host__ __device__ constexpr float S14f(int t) {
    constexpr float v[14] = {
         0.0f,
         0.4338837391175581f,  0.7818314824680298f,  0.9749279121818236f,
         0.9749279121818236f,  0.7818314824680299f,  0.4338837391175582f,
         0.0f,
        -0.4338837391175581f, -0.7818314824680298f, -0.9749279121818236f,
        -0.9749279121818236f, -0.7818314824680299f, -0.4338837391175582f
    };
    return v[t];
}

__device__ __forceinline__ ull f2pk(float a) {
    ull r; asm("mov.b64 %0, {%1, %1};" : "=l"(r) : "f"(a)); return r;
}
__device__ __forceinline__ ull f2pk2(float a, float b) {
    ull r; asm("mov.b64 %0, {%1, %2};" : "=l"(r) : "f"(a), "f"(b)); return r;
}
__device__ __forceinline__ ull f2fma(ull a, ull b, ull c) {
    ull r; asm("fma.rn.f32x2 %0, %1, %2, %3;" : "=l"(r) : "l"(a), "l"(b), "l"(c)); return r;
}
__device__ __forceinline__ ull f2mul(ull a, ull b) {
    ull r; asm("mul.rn.f32x2 %0, %1, %2;" : "=l"(r) : "l"(a), "l"(b)); return r;
}
__device__ __forceinline__ ull f2add(ull a, ull b) {
    ull r; asm("add.rn.f32x2 %0, %1, %2;" : "=l"(r) : "l"(a), "l"(b)); return r;
}
__device__ __forceinline__ ull f2neg(ull a) { return a ^ 0x8000000080000000ULL; }

#define CB      64
#define LANES   32
#define THREADS 128
#define SMEM_BYTES (14 * 16 * LANES * 8)

extern "C" __global__ void __launch_bounds__(THREADS)
gf_kernel(const float* __restrict__ x,
          const float* __restrict__ w,
          float* __restrict__ out)
{
    extern __shared__ ull S[];   // [14][16][LANES]

    const int b    = blockIdx.x;
    const int c0   = blockIdx.y * CB;
    const int tid  = threadIdx.x;
    const int lane = tid & (LANES - 1);
    const int h    = tid >> 5;           // 0..3
    const int ch   = c0 + 2 * lane;      // first of the channel pair

    // ---------------- load x[b, :, ch..ch+1] (64-bit loads) ----------------
    const float* xb = x + (size_t)b * 196 * 384 + ch;
    #pragma unroll 7
    for (int n = h * 49; n < h * 49 + 49; ++n) {
        S[((n / 14) * 16 + (n % 14)) * LANES + lane] = *(const ull*)(xb + (size_t)n * 384);
    }
    __syncthreads();

    // ---------------- stage 1: rfft along rows (a2 -> k2) ----------------
    for (int a1 = h; a1 < 14; a1 += 4) {
        ull r[14];
        #pragma unroll
        for (int j = 0; j < 14; ++j) r[j] = S[(a1 * 16 + j) * LANES + lane];

        #pragma unroll
        for (int k = 0; k < 8; ++k) {
            ull sr = r[0];       // j=0: t=0, C=1, S=0
            ull si = 0;          // packed (0,0)
            #pragma unroll
            for (int j = 1; j < 14; ++j) {
                const int t = (j * k) % 14;
                sr = f2fma(r[j], f2pk(C14f(t)), sr);
                if (S14f(t) != 0.0f) si = f2fma(r[j], f2pk(-S14f(t)), si);
            }
            S[(a1 * 16 + k)     * LANES + lane] = sr;
            S[(a1 * 16 + 8 + k) * LANES + lane] = si;
        }
    }
    __syncthreads();

    // ------- middle: per-column fwd DFT -> *w -> inverse DFT (phase A / phase B) -------
    for (int k2 = h * 2; k2 < h * 2 + 2; ++k2) {
        // ---- phase A: forward DFT along a1 + weight, write Z to rows k1 ----
        {
            ull yr[14], yi[14];
            #pragma unroll
            for (int j = 0; j < 14; ++j) {
                yr[j] = S[(j * 16 + k2)     * LANES + lane];
                yi[j] = S[(j * 16 + 8 + k2) * LANES + lane];
            }
            #pragma unroll
            for (int k1 = 0; k1 < 14; ++k1) {
                ull Xr = yr[0], Xi = yi[0];   // j=0 term
                #pragma unroll
                for (int j = 1; j < 14; ++j) {
                    const int t = (j * k1) % 14;
                    Xr = f2fma(yr[j], f2pk(C14f(t)), Xr);
                    Xi = f2fma(yi[j], f2pk(C14f(t)), Xi);
                    if (S14f(t) != 0.0f) {
                        Xr = f2fma(yi[j], f2pk( S14f(t)), Xr);
                        Xi = f2fma(yr[j], f2pk(-S14f(t)), Xi);
                    }
                }
                // complex weight for channel pair: floats (wr0,wi0,wr1,wi1)
                const float4 w4 = *(const float4*)(w + ((size_t)(k1 * 8 + k2) * 384 + ch) * 2);
                const ull wr = f2pk2(w4.x, w4.z);
                const ull wi = f2pk2(w4.y, w4.w);
                const ull Zr = f2fma(Xi, f2neg(wi), f2mul(Xr, wr));
                const ull Zi = f2fma(Xi, wr,        f2mul(Xr, wi));
                S[(k1 * 16 + k2)     * LANES + lane] = Zr;  // own slots (y[k1] dead)
                S[(k1 * 16 + 8 + k2) * LANES + lane] = Zi;
            }
        }
        // ---- phase B: inverse DFT along a1 (e^{+i}), accumulate, write back ----
        {
            ull orr[14], oii[14];
            #pragma unroll
            for (int k1 = 0; k1 < 14; ++k1) {
                const ull Zr = S[(k1 * 16 + k2)     * LANES + lane];
                const ull Zi = S[(k1 * 16 + 8 + k2) * LANES + lane];
                #pragma unroll
                for (int a1 = 0; a1 < 14; ++a1) {
                    if (k1 == 0) { orr[a1] = Zr; oii[a1] = Zi; }
                    else {
                        const int t = (k1 * a1) % 14;
                        orr[a1] = f2fma(Zr, f2pk(C14f(t)), orr[a1]);
                        oii[a1] = f2fma(Zi, f2pk(C14f(t)), oii[a1]);
                        if (S14f(t) != 0.0f) {
                            orr[a1] = f2fma(Zi, f2pk(-S14f(t)), orr[a1]);
                            oii[a1] = f2fma(Zr, f2pk( S14f(t)), oii[a1]);
                        }
                    }
                }
            }
            #pragma unroll
            for (int a1 = 0; a1 < 14; ++a1) {
                S[(a1 * 16 + k2)     * LANES + lane] = orr[a1];
                S[(a1 * 16 + 8 + k2) * LANES + lane] = oii[a1];
            }
        }
    }
    __syncthreads();

    // ---------------- stage 5: irfft along rows (k2 -> a2), store ----------------
    float* ob = out + (size_t)b * 196 * 384 + ch;
    for (int a1 = h; a1 < 14; a1 += 4) {
        ull zr[8], zi[8];
        #pragma unroll
        for (int k = 0; k < 8; ++k) {
            zr[k] = S[(a1 * 16 + k)     * LANES + lane];
            zi[k] = S[(a1 * 16 + 8 + k) * LANES + lane];
        }
        // fold the 1/196 global scale + factor-2 for interior bins into prescale
        const ull s1 = f2pk(1.0f / 196.0f);
        const ull s2 = f2pk(2.0f / 196.0f);
        zr[0] = f2mul(zr[0], s1);
        zr[7] = f2mul(zr[7], s1);
        #pragma unroll
        for (int k = 1; k < 7; ++k) { zr[k] = f2mul(zr[k], s2); zi[k] = f2mul(zi[k], s2); }

        #pragma unroll
        for (int a2 = 0; a2 < 14; ++a2) {
            ull v = (a2 & 1) ? f2fma(zr[7], f2pk(-1.0f), zr[0]) : f2add(zr[0], zr[7]);
            #pragma unroll
            for (int k = 1; k < 7; ++k) {
                const int t = (k * a2) % 14;
                v = f2fma(zr[k], f2pk(C14f(t)), v);
                if (S14f(t) != 0.0f) v = f2fma(zi[k], f2pk(-S14f(t)), v);
            }
            *(ull*)(ob + (size_t)(a1 * 14 + a2) * 384) = v;
        }
    }
}

extern "C" void kernel_launch(void* const* d_in, const int* in_sizes, int n_in,
                              void* d_out, int out_size)
{
    const float* x = (const float*)d_in[0];   // [512,196,384] f32
    const float* w = (const float*)d_in[1];   // [14,8,384,2]  f32
    float* out = (float*)d_out;               // [512,196,384] f32

    cudaFuncSetAttribute(gf_kernel, cudaFuncAttributeMaxDynamicSharedMemorySize, SMEM_BYTES);

    dim3 grid(512, 384 / CB);
    gf_kernel<<<grid, THREADS, SMEM_BYTES>>>(x, w, out);
}

// round 4
// speedup vs baseline: 3.0107x; 1.1944x over previous
#include <cuda_runtime.h>

// GlobalFilter: out = IDFT2( DFT2(x) * w ) / 196 on 14x14 grids, fused, f32x2-packed,
// with even/odd (cos/sin) symmetry folding in all four DFT stages (~2.2x fewer FMAs).
//
// CTA = (batch, 64-channel block). 128 threads = 32 lane-pairs x 4 work groups (h).
// smem tile S[row(14)][slot(16)][lane(32)] of ull (packed 2xf32): 57344 B.

typedef unsigned long long ull;

__host__ __device__ constexpr float C14f(int t) {
    constexpr float v[14] = {
         1.0f,
         0.9009688679024191f,  0.6234898018587336f,  0.22252093395631445f,
        -0.22252093395631434f, -0.6234898018587335f, -0.9009688679024190f,
        -1.0f,
        -0.9009688679024191f, -0.6234898018587336f, -0.22252093395631445f,
         0.22252093395631434f,  0.6234898018587335f,  0.9009688679024190f
    };
    return v[t];
}
__host__ __device__ constexpr float S14f(int t) {
    constexpr float v[14] = {
         0.0f,
         0.4338837391175581f,  0.7818314824680298f,  0.9749279121818236f,
         0.9749279121818236f,  0.7818314824680299f,  0.4338837391175582f,
         0.0f,
        -0.4338837391175581f, -0.7818314824680298f, -0.9749279121818236f,
        -0.9749279121818236f, -0.7818314824680299f, -0.4338837391175582f
    };
    return v[t];
}

__device__ __forceinline__ ull f2pk(float a) {
    ull r; asm("mov.b64 %0, {%1, %1};" : "=l"(r) : "f"(a)); return r;
}
__device__ __forceinline__ ull f2pk2(float a, float b) {
    ull r; asm("mov.b64 %0, {%1, %2};" : "=l"(r) : "f"(a), "f"(b)); return r;
}
__device__ __forceinline__ ull f2fma(ull a, ull b, ull c) {
    ull r; asm("fma.rn.f32x2 %0, %1, %2, %3;" : "=l"(r) : "l"(a), "l"(b), "l"(c)); return r;
}
__device__ __forceinline__ ull f2mul(ull a, ull b) {
    ull r; asm("mul.rn.f32x2 %0, %1, %2;" : "=l"(r) : "l"(a), "l"(b)); return r;
}
__device__ __forceinline__ ull f2add(ull a, ull b) {
    ull r; asm("add.rn.f32x2 %0, %1, %2;" : "=l"(r) : "l"(a), "l"(b)); return r;
}
__device__ __forceinline__ ull f2sub(ull a, ull b) {
    ull r; asm("sub.rn.f32x2 %0, %1, %2;" : "=l"(r) : "l"(a), "l"(b)); return r;
}
__device__ __forceinline__ ull f2neg(ull a) { return a ^ 0x8000000080000000ULL; }

#define CB      64
#define LANES   32
#define THREADS 128
#define SMEM_BYTES (14 * 16 * LANES * 8)

extern "C" __global__ void __launch_bounds__(THREADS)
gf_kernel(const float* __restrict__ x,
          const float* __restrict__ w,
          float* __restrict__ out)
{
    extern __shared__ ull S[];   // [14][16][LANES]

    const int b    = blockIdx.x;
    const int c0   = blockIdx.y * CB;
    const int tid  = threadIdx.x;
    const int lane = tid & (LANES - 1);
    const int h    = tid >> 5;           // 0..3
    const int ch   = c0 + 2 * lane;

    // ---------------- load x[b, :, ch..ch+1] ----------------
    const float* xb = x + (size_t)b * 196 * 384 + ch;
    #pragma unroll 7
    for (int n = h * 49; n < h * 49 + 49; ++n) {
        S[((n / 14) * 16 + (n % 14)) * LANES + lane] = *(const ull*)(xb + (size_t)n * 384);
    }
    __syncthreads();

    // ---------------- stage 1: real DFT along rows (a2 -> k2), folded ----------------
    for (int a1 = h; a1 < 14; a1 += 4) {
        ull r[14];
        #pragma unroll
        for (int j = 0; j < 14; ++j) r[j] = S[(a1 * 16 + j) * LANES + lane];

        const ull p = f2add(r[0], r[7]);
        const ull m = f2sub(r[0], r[7]);
        ull e[7], o[7];
        #pragma unroll
        for (int j = 1; j < 7; ++j) { e[j] = f2add(r[j], r[14 - j]); o[j] = f2sub(r[j], r[14 - j]); }

        // k = 0 : re = p + sum e ; im = 0
        {
            ull sr = p;
            #pragma unroll
            for (int j = 1; j < 7; ++j) sr = f2add(sr, e[j]);
            S[(a1 * 16 + 0) * LANES + lane] = sr;
            S[(a1 * 16 + 8) * LANES + lane] = 0ULL;
        }
        // k = 7 : re = m + sum (-1)^j e ; im = 0
        {
            ull sr = m;
            #pragma unroll
            for (int j = 1; j < 7; ++j) sr = (j & 1) ? f2sub(sr, e[j]) : f2add(sr, e[j]);
            S[(a1 * 16 + 7)  * LANES + lane] = sr;
            S[(a1 * 16 + 15) * LANES + lane] = 0ULL;
        }
        // k = 1..6
        #pragma unroll
        for (int k = 1; k < 7; ++k) {
            ull sr = (k & 1) ? m : p;
            ull si;
            #pragma unroll
            for (int j = 1; j < 7; ++j) {
                const int t = (j * k) % 14;
                sr = f2fma(e[j], f2pk(C14f(t)), sr);
                if (j == 1) si = f2mul(o[1], f2pk(-S14f(t)));
                else        si = f2fma(o[j], f2pk(-S14f(t)), si);
            }
            S[(a1 * 16 + k)     * LANES + lane] = sr;
            S[(a1 * 16 + 8 + k) * LANES + lane] = si;
        }
    }
    __syncthreads();

    // ------- middle: per-column fwd DFT -> *w (phase A), inverse DFT (phase B) -------
    for (int k2 = h * 2; k2 < h * 2 + 2; ++k2) {
        // ==== phase A: forward 14-pt complex DFT along a1 + weight, folded ====
        {
            ull yr[14], yi[14];
            #pragma unroll
            for (int j = 0; j < 14; ++j) {
                yr[j] = S[(j * 16 + k2)     * LANES + lane];
                yi[j] = S[(j * 16 + 8 + k2) * LANES + lane];
            }
            const ull pr = f2add(yr[0], yr[7]), mr = f2sub(yr[0], yr[7]);
            const ull pi = f2add(yi[0], yi[7]), mi = f2sub(yi[0], yi[7]);
            ull Er[7], Ei[7], Or[7], Oi[7];
            #pragma unroll
            for (int j = 1; j < 7; ++j) {
                Er[j] = f2add(yr[j], yr[14 - j]); Or[j] = f2sub(yr[j], yr[14 - j]);
                Ei[j] = f2add(yi[j], yi[14 - j]); Oi[j] = f2sub(yi[j], yi[14 - j]);
            }

            // helper lambda: weight-multiply X and store Z at row k1
            auto wmul_store = [&](int k1, ull Xr, ull Xi) {
                const float4 w4 = *(const float4*)(w + ((size_t)(k1 * 8 + k2) * 384 + ch) * 2);
                const ull wr = f2pk2(w4.x, w4.z);
                const ull wi = f2pk2(w4.y, w4.w);
                const ull Zr = f2fma(Xi, f2neg(wi), f2mul(Xr, wr));
                const ull Zi = f2fma(Xi, wr,        f2mul(Xr, wi));
                S[(k1 * 16 + k2)     * LANES + lane] = Zr;
                S[(k1 * 16 + 8 + k2) * LANES + lane] = Zi;
            };

            // k1 = 0
            {
                ull Xr = pr, Xi = pi;
                #pragma unroll
                for (int j = 1; j < 7; ++j) { Xr = f2add(Xr, Er[j]); Xi = f2add(Xi, Ei[j]); }
                wmul_store(0, Xr, Xi);
            }
            // k1 = 7
            {
                ull Xr = mr, Xi = mi;
                #pragma unroll
                for (int j = 1; j < 7; ++j) {
                    if (j & 1) { Xr = f2sub(Xr, Er[j]); Xi = f2sub(Xi, Ei[j]); }
                    else       { Xr = f2add(Xr, Er[j]); Xi = f2add(Xi, Ei[j]); }
                }
                wmul_store(7, Xr, Xi);
            }
            // pairs k1 / 14-k1
            #pragma unroll
            for (int k1 = 1; k1 < 7; ++k1) {
                ull Ar = (k1 & 1) ? mr : pr;
                ull Ai = (k1 & 1) ? mi : pi;
                ull Br, Bi;
                #pragma unroll
                for (int j = 1; j < 7; ++j) {
                    const int t = (j * k1) % 14;
                    Ar = f2fma(Er[j], f2pk(C14f(t)), Ar);
                    Ai = f2fma(Ei[j], f2pk(C14f(t)), Ai);
                    if (j == 1) { Br = f2mul(Or[1], f2pk(S14f(t))); Bi = f2mul(Oi[1], f2pk(S14f(t))); }
                    else        { Br = f2fma(Or[j], f2pk(S14f(t)), Br); Bi = f2fma(Oi[j], f2pk(S14f(t)), Bi); }
                }
                // X[k1] = A - iB ; X[14-k1] = A + iB
                wmul_store(k1,      f2add(Ar, Bi), f2sub(Ai, Br));
                wmul_store(14 - k1, f2sub(Ar, Bi), f2add(Ai, Br));
            }
        }
        // ==== phase B: inverse 14-pt complex DFT along a1 (e^{+i}), folded ====
        {
            ull Zr[14], Zi[14];
            #pragma unroll
            for (int k = 0; k < 14; ++k) {
                Zr[k] = S[(k * 16 + k2)     * LANES + lane];
                Zi[k] = S[(k * 16 + 8 + k2) * LANES + lane];
            }
            const ull pr = f2add(Zr[0], Zr[7]), mr = f2sub(Zr[0], Zr[7]);
            const ull pi = f2add(Zi[0], Zi[7]), mi = f2sub(Zi[0], Zi[7]);
            ull Er[7], Ei[7], Or[7], Oi[7];
            #pragma unroll
            for (int k = 1; k < 7; ++k) {
                Er[k] = f2add(Zr[k], Zr[14 - k]); Or[k] = f2sub(Zr[k], Zr[14 - k]);
                Ei[k] = f2add(Zi[k], Zi[14 - k]); Oi[k] = f2sub(Zi[k], Zi[14 - k]);
            }

            // a1 = 0
            {
                ull zr = pr, zi = pi;
                #pragma unroll
                for (int k = 1; k < 7; ++k) { zr = f2add(zr, Er[k]); zi = f2add(zi, Ei[k]); }
                S[(0 * 16 + k2)     * LANES + lane] = zr;
                S[(0 * 16 + 8 + k2) * LANES + lane] = zi;
            }
            // a1 = 7
            {
                ull zr = mr, zi = mi;
                #pragma unroll
                for (int k = 1; k < 7; ++k) {
                    if (k & 1) { zr = f2sub(zr, Er[k]); zi = f2sub(zi, Ei[k]); }
                    else       { zr = f2add(zr, Er[k]); zi = f2add(zi, Ei[k]); }
                }
                S[(7 * 16 + k2)     * LANES + lane] = zr;
                S[(7 * 16 + 8 + k2) * LANES + lane] = zi;
            }
            // pairs a1 / 14-a1
            #pragma unroll
            for (int a1 = 1; a1 < 7; ++a1) {
                ull Ar = (a1 & 1) ? mr : pr;
                ull Ai = (a1 & 1) ? mi : pi;
                ull Br, Bi;
                #pragma unroll
                for (int k = 1; k < 7; ++k) {
                    const int t = (k * a1) % 14;
                    Ar = f2fma(Er[k], f2pk(C14f(t)), Ar);
                    Ai = f2fma(Ei[k], f2pk(C14f(t)), Ai);
                    if (k == 1) { Br = f2mul(Or[1], f2pk(S14f(t))); Bi = f2mul(Oi[1], f2pk(S14f(t))); }
                    else        { Br = f2fma(Or[k], f2pk(S14f(t)), Br); Bi = f2fma(Oi[k], f2pk(S14f(t)), Bi); }
                }
                // z[a1] = A + iB ; z[14-a1] = A - iB
                S[(a1 * 16 + k2)            * LANES + lane] = f2sub(Ar, Bi);
                S[(a1 * 16 + 8 + k2)        * LANES + lane] = f2add(Ai, Br);
                S[((14 - a1) * 16 + k2)     * LANES + lane] = f2add(Ar, Bi);
                S[((14 - a1) * 16 + 8 + k2) * LANES + lane] = f2sub(Ai, Br);
            }
        }
    }
    __syncthreads();

    // ---------------- stage 5: irfft along rows (k2 -> a2), folded, store ----------------
    float* ob = out + (size_t)b * 196 * 384 + ch;
    for (int a1 = h; a1 < 14; a1 += 4) {
        ull zr[8], zi[8];
        #pragma unroll
        for (int k = 0; k < 8; ++k) {
            zr[k] = S[(a1 * 16 + k)     * LANES + lane];
            zi[k] = S[(a1 * 16 + 8 + k) * LANES + lane];
        }
        const ull s1 = f2pk(1.0f / 196.0f);
        const ull s2 = f2pk(2.0f / 196.0f);
        zr[0] = f2mul(zr[0], s1);
        zr[7] = f2mul(zr[7], s1);
        #pragma unroll
        for (int k = 1; k < 7; ++k) { zr[k] = f2mul(zr[k], s2); zi[k] = f2mul(zi[k], s2); }

        const ull p = f2add(zr[0], zr[7]);
        const ull m = f2sub(zr[0], zr[7]);

        // a2 = 0
        {
            ull v = p;
            #pragma unroll
            for (int k = 1; k < 7; ++k) v = f2add(v, zr[k]);
            *(ull*)(ob + (size_t)(a1 * 14 + 0) * 384) = v;
        }
        // a2 = 7
        {
            ull v = m;
            #pragma unroll
            for (int k = 1; k < 7; ++k) v = (k & 1) ? f2sub(v, zr[k]) : f2add(v, zr[k]);
            *(ull*)(ob + (size_t)(a1 * 14 + 7) * 384) = v;
        }
        // pairs a2 / 14-a2
        #pragma unroll
        for (int a2 = 1; a2 < 7; ++a2) {
            ull E = (a2 & 1) ? m : p;
            ull Od;
            #pragma unroll
            for (int k = 1; k < 7; ++k) {
                const int t = (k * a2) % 14;
                E = f2fma(zr[k], f2pk(C14f(t)), E);
                if (k == 1) Od = f2mul(zi[1], f2pk(-S14f(t)));
                else        Od = f2fma(zi[k], f2pk(-S14f(t)), Od);
            }
            *(ull*)(ob + (size_t)(a1 * 14 + a2)        * 384) = f2add(E, Od);
            *(ull*)(ob + (size_t)(a1 * 14 + (14 - a2)) * 384) = f2sub(E, Od);
        }
    }
}

extern "C" void kernel_launch(void* const* d_in, const int* in_sizes, int n_in,
                              void* d_out, int out_size)
{
    const float* x = (const float*)d_in[0];   // [512,196,384] f32
    const float* w = (const float*)d_in[1];   // [14,8,384,2]  f32
    float* out = (float*)d_out;               // [512,196,384] f32

    cudaFuncSetAttribute(gf_kernel, cudaFuncAttributeMaxDynamicSharedMemorySize, SMEM_BYTES);

    dim3 grid(512, 384 / CB);
    gf_kernel<<<grid, THREADS, SMEM_BYTES>>>(x, w, out);
}

// round 6
// speedup vs baseline: 3.0211x; 1.0035x over previous
#include <cuda_runtime.h>

// GlobalFilter: out = IDFT2( DFT2(x) * w ) / 196 on 14x14 grids.
// f32x2-packed (2 channels/thread), even/odd folded in all stages, and the
// middle column transform (fwd DFT -> *w -> inv DFT) fully fused in registers.
//
// CTA = (batch, 64-channel block). 128 threads = 32 lane-pairs x 4 groups (h).
// smem tile S[row(14)][slot(16)][lane(32)] of ull: 57344 B -> 3 CTAs/SM.

typedef unsigned long long ull;

__host__ __device__ constexpr float C14f(int t) {
    constexpr float v[14] = {
         1.0f,
         0.9009688679024191f,  0.6234898018587336f,  0.22252093395631445f,
        -0.22252093395631434f, -0.6234898018587335f, -0.9009688679024190f,
        -1.0f,
        -0.9009688679024191f, -0.6234898018587336f, -0.22252093395631445f,
         0.22252093395631434f,  0.6234898018587335f,  0.9009688679024190f
    };
    return v[t];
}
__host__ __device__ constexpr float S14f(int t) {
    constexpr float v[14] = {
         0.0f,
         0.4338837391175581f,  0.7818314824680298f,  0.9749279121818236f,
         0.9749279121818236f,  0.7818314824680299f,  0.4338837391175582f,
         0.0f,
        -0.4338837391175581f, -0.7818314824680298f, -0.9749279121818236f,
        -0.9749279121818236f, -0.7818314824680299f, -0.4338837391175582f
    };
    return v[t];
}

__device__ __forceinline__ ull f2pk(float a) {
    ull r; asm("mov.b64 %0, {%1, %1};" : "=l"(r) : "f"(a)); return r;
}
__device__ __forceinline__ ull f2pk2(float a, float b) {
    ull r; asm("mov.b64 %0, {%1, %2};" : "=l"(r) : "f"(a), "f"(b)); return r;
}
__device__ __forceinline__ ull f2fma(ull a, ull b, ull c) {
    ull r; asm("fma.rn.f32x2 %0, %1, %2, %3;" : "=l"(r) : "l"(a), "l"(b), "l"(c)); return r;
}
__device__ __forceinline__ ull f2mul(ull a, ull b) {
    ull r; asm("mul.rn.f32x2 %0, %1, %2;" : "=l"(r) : "l"(a), "l"(b)); return r;
}
__device__ __forceinline__ ull f2add(ull a, ull b) {
    ull r; asm("add.rn.f32x2 %0, %1, %2;" : "=l"(r) : "l"(a), "l"(b)); return r;
}
__device__ __forceinline__ ull f2sub(ull a, ull b) {
    ull r; asm("sub.rn.f32x2 %0, %1, %2;" : "=l"(r) : "l"(a), "l"(b)); return r;
}
__device__ __forceinline__ ull f2neg(ull a) { return a ^ 0x8000000080000000ULL; }

// accumulate acc += v * C14f(t), exploiting C = +/-1 cases
__device__ __forceinline__ ull f2accC(ull acc, ull v, int t) {
    if (C14f(t) ==  1.0f) return f2add(acc, v);
    if (C14f(t) == -1.0f) return f2sub(acc, v);
    return f2fma(v, f2pk(C14f(t)), acc);
}

#define CB      64
#define LANES   32
#define THREADS 128
#define SMEM_BYTES (14 * 16 * LANES * 8)

extern "C" __global__ void __launch_bounds__(THREADS, 3)
gf_kernel(const float* __restrict__ x,
          const float* __restrict__ w,
          float* __restrict__ out)
{
    extern __shared__ ull S[];   // [14][16][LANES]

    const int b    = blockIdx.x;
    const int c0   = blockIdx.y * CB;
    const int tid  = threadIdx.x;
    const int lane = tid & (LANES - 1);
    const int h    = tid >> 5;           // 0..3
    const int ch   = c0 + 2 * lane;

    // ---------------- load x[b, :, ch..ch+1] ----------------
    const float* xb = x + (size_t)b * 196 * 384 + ch;
    #pragma unroll 7
    for (int n = h * 49; n < h * 49 + 49; ++n) {
        S[((n / 14) * 16 + (n % 14)) * LANES + lane] = *(const ull*)(xb + (size_t)n * 384);
    }
    __syncthreads();

    // ---------------- stage 1: real DFT along rows (a2 -> k2), folded ----------------
    for (int a1 = h; a1 < 14; a1 += 4) {
        ull r[14];
        #pragma unroll
        for (int j = 0; j < 14; ++j) r[j] = S[(a1 * 16 + j) * LANES + lane];

        const ull p = f2add(r[0], r[7]);
        const ull m = f2sub(r[0], r[7]);
        ull e[7], o[7];
        #pragma unroll
        for (int j = 1; j < 7; ++j) { e[j] = f2add(r[j], r[14 - j]); o[j] = f2sub(r[j], r[14 - j]); }

        // k = 0
        {
            ull sr = p;
            #pragma unroll
            for (int j = 1; j < 7; ++j) sr = f2add(sr, e[j]);
            S[(a1 * 16 + 0) * LANES + lane] = sr;
            S[(a1 * 16 + 8) * LANES + lane] = 0ULL;
        }
        // k = 7
        {
            ull sr = m;
            #pragma unroll
            for (int j = 1; j < 7; ++j) sr = (j & 1) ? f2sub(sr, e[j]) : f2add(sr, e[j]);
            S[(a1 * 16 + 7)  * LANES + lane] = sr;
            S[(a1 * 16 + 15) * LANES + lane] = 0ULL;
        }
        // k = 1..6
        #pragma unroll
        for (int k = 1; k < 7; ++k) {
            ull sr = (k & 1) ? m : p;
            ull si;
            #pragma unroll
            for (int j = 1; j < 7; ++j) {
                const int t = (j * k) % 14;
                sr = f2fma(e[j], f2pk(C14f(t)), sr);
                if (j == 1) si = f2mul(o[1], f2pk(-S14f(t)));
                else        si = f2fma(o[j], f2pk(-S14f(t)), si);
            }
            S[(a1 * 16 + k)     * LANES + lane] = sr;
            S[(a1 * 16 + 8 + k) * LANES + lane] = si;
        }
    }
    __syncthreads();

    // ------- middle (FUSED): per-column fwd DFT -> *w -> inverse DFT, all in regs -------
    for (int k2 = h * 2; k2 < h * 2 + 2; ++k2) {
        // load column and fold input side
        ull pr, mr, pi, mi, Er[7], Ei[7], Or[7], Oi[7];
        {
            ull yr[14], yi[14];
            #pragma unroll
            for (int j = 0; j < 14; ++j) {
                yr[j] = S[(j * 16 + k2)     * LANES + lane];
                yi[j] = S[(j * 16 + 8 + k2) * LANES + lane];
            }
            pr = f2add(yr[0], yr[7]); mr = f2sub(yr[0], yr[7]);
            pi = f2add(yi[0], yi[7]); mi = f2sub(yi[0], yi[7]);
            #pragma unroll
            for (int j = 1; j < 7; ++j) {
                Er[j] = f2add(yr[j], yr[14 - j]); Or[j] = f2sub(yr[j], yr[14 - j]);
                Ei[j] = f2add(yi[j], yi[14 - j]); Oi[j] = f2sub(yi[j], yi[14 - j]);
            }
        }

        const float* wcol = w + ((size_t)k2 * 384 + ch) * 2;   // + k1*8*384*2 per row

        // k1 = 0 and k1 = 7 terms -> init CP accumulators
        ull CPr[8], CPi[8], SQr[7], SQi[7];
        {
            ull X0r = pr, X0i = pi, X7r = mr, X7i = mi;
            #pragma unroll
            for (int j = 1; j < 7; ++j) {
                X0r = f2add(X0r, Er[j]); X0i = f2add(X0i, Ei[j]);
                if (j & 1) { X7r = f2sub(X7r, Er[j]); X7i = f2sub(X7i, Ei[j]); }
                else       { X7r = f2add(X7r, Er[j]); X7i = f2add(X7i, Ei[j]); }
            }
            const float4 w0 = *(const float4*)(wcol + (size_t)0 * 8 * 384 * 2);
            const float4 w7 = *(const float4*)(wcol + (size_t)7 * 8 * 384 * 2);
            const ull w0r = f2pk2(w0.x, w0.z), w0i = f2pk2(w0.y, w0.w);
            const ull w7r = f2pk2(w7.x, w7.z), w7i = f2pk2(w7.y, w7.w);
            const ull Z0r = f2fma(X0i, f2neg(w0i), f2mul(X0r, w0r));
            const ull Z0i = f2fma(X0i, w0r,        f2mul(X0r, w0i));
            const ull Z7r = f2fma(X7i, f2neg(w7i), f2mul(X7r, w7r));
            const ull Z7i = f2fma(X7i, w7r,        f2mul(X7r, w7i));
            const ull epr = f2add(Z0r, Z7r), emr = f2sub(Z0r, Z7r);
            const ull epi = f2add(Z0i, Z7i), emi = f2sub(Z0i, Z7i);
            #pragma unroll
            for (int a1 = 0; a1 < 8; ++a1) {
                CPr[a1] = (a1 & 1) ? emr : epr;
                CPi[a1] = (a1 & 1) ? emi : epi;
            }
        }

        // k1 pairs (k1, 14-k1), k1 = 1..6
        #pragma unroll
        for (int k1 = 1; k1 < 7; ++k1) {
            ull Ar = (k1 & 1) ? mr : pr;
            ull Ai = (k1 & 1) ? mi : pi;
            ull Br, Bi;
            #pragma unroll
            for (int j = 1; j < 7; ++j) {
                const int t = (j * k1) % 14;
                Ar = f2fma(Er[j], f2pk(C14f(t)), Ar);
                Ai = f2fma(Ei[j], f2pk(C14f(t)), Ai);
                if (j == 1) { Br = f2mul(Or[1], f2pk(S14f(t))); Bi = f2mul(Oi[1], f2pk(S14f(t))); }
                else        { Br = f2fma(Or[j], f2pk(S14f(t)), Br); Bi = f2fma(Oi[j], f2pk(S14f(t)), Bi); }
            }
            // X[k1] = A - iB, X[14-k1] = A + iB
            const ull X1r = f2add(Ar, Bi), X1i = f2sub(Ai, Br);
            const ull X2r = f2sub(Ar, Bi), X2i = f2add(Ai, Br);
            // weights
            const float4 wa = *(const float4*)(wcol + (size_t)k1        * 8 * 384 * 2);
            const float4 wb = *(const float4*)(wcol + (size_t)(14 - k1) * 8 * 384 * 2);
            const ull war = f2pk2(wa.x, wa.z), wai = f2pk2(wa.y, wa.w);
            const ull wbr = f2pk2(wb.x, wb.z), wbi = f2pk2(wb.y, wb.w);
            const ull Z1r = f2fma(X1i, f2neg(wai), f2mul(X1r, war));
            const ull Z1i = f2fma(X1i, war,        f2mul(X1r, wai));
            const ull Z2r = f2fma(X2i, f2neg(wbi), f2mul(X2r, wbr));
            const ull Z2i = f2fma(X2i, wbr,        f2mul(X2r, wbi));
            // fold Z pair for the inverse transform
            const ull Ezr = f2add(Z1r, Z2r), Ezi = f2add(Z1i, Z2i);
            const ull Ozr = f2sub(Z1r, Z2r), Ozi = f2sub(Z1i, Z2i);
            // accumulate
            #pragma unroll
            for (int a1 = 0; a1 < 8; ++a1) {
                const int t = (k1 * a1) % 14;
                CPr[a1] = f2accC(CPr[a1], Ezr, t);
                CPi[a1] = f2accC(CPi[a1], Ezi, t);
            }
            #pragma unroll
            for (int a1 = 1; a1 < 7; ++a1) {
                const int t = (k1 * a1) % 14;
                if (k1 == 1) { SQr[a1] = f2mul(Ozr, f2pk(S14f(t))); SQi[a1] = f2mul(Ozi, f2pk(S14f(t))); }
                else         { SQr[a1] = f2fma(Ozr, f2pk(S14f(t)), SQr[a1]); SQi[a1] = f2fma(Ozi, f2pk(S14f(t)), SQi[a1]); }
            }
        }

        // write z rows back:
        // z[0] = CP[0]; z[7] = CP[7]
        S[(0 * 16 + k2)     * LANES + lane] = CPr[0];
        S[(0 * 16 + 8 + k2) * LANES + lane] = CPi[0];
        S[(7 * 16 + k2)     * LANES + lane] = CPr[7];
        S[(7 * 16 + 8 + k2) * LANES + lane] = CPi[7];
        // z[a1] = CP - i*...: z[a1] = (CPr - SQi, CPi + SQr); z[14-a1] = (CPr + SQi, CPi - SQr)
        #pragma unroll
        for (int a1 = 1; a1 < 7; ++a1) {
            S[(a1 * 16 + k2)            * LANES + lane] = f2sub(CPr[a1], SQi[a1]);
            S[(a1 * 16 + 8 + k2)        * LANES + lane] = f2add(CPi[a1], SQr[a1]);
            S[((14 - a1) * 16 + k2)     * LANES + lane] = f2add(CPr[a1], SQi[a1]);
            S[((14 - a1) * 16 + 8 + k2) * LANES + lane] = f2sub(CPi[a1], SQr[a1]);
        }
    }
    __syncthreads();

    // ---------------- stage 5: irfft along rows (k2 -> a2), folded, store ----------------
    float* ob = out + (size_t)b * 196 * 384 + ch;
    for (int a1 = h; a1 < 14; a1 += 4) {
        ull zr[8], zi[8];
        #pragma unroll
        for (int k = 0; k < 8; ++k) {
            zr[k] = S[(a1 * 16 + k)     * LANES + lane];
            zi[k] = S[(a1 * 16 + 8 + k) * LANES + lane];
        }
        const ull s1 = f2pk(1.0f / 196.0f);
        const ull s2 = f2pk(2.0f / 196.0f);
        zr[0] = f2mul(zr[0], s1);
        zr[7] = f2mul(zr[7], s1);
        #pragma unroll
        for (int k = 1; k < 7; ++k) { zr[k] = f2mul(zr[k], s2); zi[k] = f2mul(zi[k], s2); }

        const ull p = f2add(zr[0], zr[7]);
        const ull m = f2sub(zr[0], zr[7]);

        // a2 = 0
        {
            ull v = p;
            #pragma unroll
            for (int k = 1; k < 7; ++k) v = f2add(v, zr[k]);
            *(ull*)(ob + (size_t)(a1 * 14 + 0) * 384) = v;
        }
        // a2 = 7
        {
            ull v = m;
            #pragma unroll
            for (int k = 1; k < 7; ++k) v = (k & 1) ? f2sub(v, zr[k]) : f2add(v, zr[k]);
            *(ull*)(ob + (size_t)(a1 * 14 + 7) * 384) = v;
        }
        // pairs a2 / 14-a2
        #pragma unroll
        for (int a2 = 1; a2 < 7; ++a2) {
            ull E = (a2 & 1) ? m : p;
            ull Od;
            #pragma unroll
            for (int k = 1; k < 7; ++k) {
                const int t = (k * a2) % 14;
                E = f2fma(zr[k], f2pk(C14f(t)), E);
                if (k == 1) Od = f2mul(zi[1], f2pk(-S14f(t)));
                else        Od = f2fma(zi[k], f2pk(-S14f(t)), Od);
            }
            *(ull*)(ob + (size_t)(a1 * 14 + a2)        * 384) = f2add(E, Od);
            *(ull*)(ob + (size_t)(a1 * 14 + (14 - a2)) * 384) = f2sub(E, Od);
        }
    }
}

extern "C" void kernel_launch(void* const* d_in, const int* in_sizes, int n_in,
                              void* d_out, int out_size)
{
    const float* x = (const float*)d_in[0];   // [512,196,384] f32
    const float* w = (const float*)d_in[1];   // [14,8,384,2]  f32
    float* out = (float*)d_out;               // [512,196,384] f32

    cudaFuncSetAttribute(gf_kernel, cudaFuncAttributeMaxDynamicSharedMemorySize, SMEM_BYTES);

    dim3 grid(512, 384 / CB);
    gf_kernel<<<grid, THREADS, SMEM_BYTES>>>(x, w, out);
}